// round 14
// baseline (speedup 1.0000x reference)
#include <cuda_runtime.h>
#include <cuda_bf16.h>

#define Bn   8
#define Cn   256
#define Gn   32
#define CPG  8
#define Hn   56
#define Wn   56
#define HWn  3136          // 56*56
#define QW   14
#define ROWS 8             // output rows per block
#define BTH  448           // 14 q * 8 r * 4 jp
#define NBLK (Bn*Gn*(Hn/ROWS))   // 1792
#define CSTR 568           // smem channel stride in floats (10*56 + 8 pad)
#define NSTG (CPG*10*QW)   // 1120 float4 staging elements

__global__ __launch_bounds__(BTH, 2)
void SKA_20950850470021_kernel(const float* __restrict__ x,
                               const float* __restrict__ w,
                               float* __restrict__ out) {
    __shared__ float sx[CPG * CSTR];   // 18176 B: 8 ch x 10 rows x 56 (+pad)

    const int tid = threadIdx.x;
    const int bid = blockIdx.x;
    const int ht = bid % (Hn / ROWS);
    const int g  = (bid / (Hn / ROWS)) % Gn;
    const int b  = bid / ((Hn / ROWS) * Gn);
    const int h0 = ht * ROWS;

    const int q  = tid % QW;           // quad in row (lane-adjacent)
    const int rj = tid / QW;
    const int r  = rj % ROWS;          // output row in tile
    const int jp = rj / ROWS;          // 0..3 : which channel pair
    const int h  = h0 + r;
    const int w0 = q * 4;
    const int lane = tid & 31;

    const int cb = (b * Cn + g) * HWn;

    // ---------- phase 1: batch the x-staging loads (<=3 float4 per thread) ----------
    float4 stg[3];
    int    sofs[3];
#pragma unroll
    for (int i = 0; i < 3; ++i) {
        int f = i * BTH + tid;         // 0..1343, valid < 1120
        bool valid = (f < NSTG);
        int jj  = f / 140;             // channel 0..7
        int rem = f % 140;
        int ri  = rem / 14;            // smem row 0..9  (image row h0-1+ri)
        int c4  = rem % 14;
        int hh  = h0 - 1 + ri;
        float4 v = make_float4(0.f, 0.f, 0.f, 0.f);
        if (valid && hh >= 0 && hh < Hn)
            v = *reinterpret_cast<const float4*>(x + cb + jj * (Gn * HWn) + hh * Wn + c4 * 4);
        stg[i]  = v;
        sofs[i] = valid ? (jj * CSTR + ri * Wn + c4 * 4) : (CPG * CSTR - 4);
    }

    // ---------- phase 2: batch the 9 per-pixel weight quads ----------
    const float* wbase = w + ((b * Gn + g) * 9) * HWn + h * Wn + w0;
    float4 wk[9];
#pragma unroll
    for (int k = 0; k < 9; ++k)
        wk[k] = *reinterpret_cast<const float4*>(wbase + k * HWn);

    // ---------- phase 3: commit staging to smem ----------
#pragma unroll
    for (int i = 0; i < 3; ++i)
        if (sofs[i] != (CPG * CSTR - 4) || i < 2)
            *reinterpret_cast<float4*>(sx + sofs[i]) = stg[i];
    __syncthreads();

    // ---------- phase 4: compute (x from smem + shuffles, w from registers) ----------
    const float hasLf = (q > 0) ? 1.f : 0.f;
    const float hasRf = (q < QW - 1) ? 1.f : 0.f;
    const bool needL = (lane == 0)  && (q > 0);
    const bool needR = (lane == 31) && (q < QW - 1);

    float4 acc[2];
    acc[0] = make_float4(0.f, 0.f, 0.f, 0.f);
    acc[1] = make_float4(0.f, 0.f, 0.f, 0.f);

#pragma unroll
    for (int j = 0; j < 2; ++j) {
        const float* sc = sx + (jp * 2 + j) * CSTR;
#pragma unroll
        for (int rr = 0; rr < 3; ++rr) {
            const float* srow = sc + (r + rr) * Wn;   // image row h-1+rr (zero-filled OOB)
            float4 c = *reinterpret_cast<const float4*>(srow + w0);
            float lv = __shfl_up_sync(0xFFFFFFFFu, c.w, 1);
            float rv = __shfl_down_sync(0xFFFFFFFFu, c.x, 1);
            if (needL) lv = srow[w0 - 1];
            if (needR) rv = srow[w0 + 4];
            lv *= hasLf;   // zeros image borders and cross-row shuffle garbage
            rv *= hasRf;

            const float4 wk0 = wk[rr * 3 + 0];
            const float4 wk1 = wk[rr * 3 + 1];
            const float4 wk2 = wk[rr * 3 + 2];
            acc[j].x += lv  * wk0.x + c.x * wk1.x + c.y * wk2.x;
            acc[j].y += c.x * wk0.y + c.y * wk1.y + c.z * wk2.y;
            acc[j].z += c.y * wk0.z + c.z * wk1.z + c.w * wk2.z;
            acc[j].w += c.z * wk0.w + c.w * wk1.w + rv  * wk2.w;
        }
    }

    // ---------- stores: 2 channels ----------
    const int obase = cb + h * Wn + w0;
#pragma unroll
    for (int j = 0; j < 2; ++j)
        *reinterpret_cast<float4*>(out + obase + (jp * 2 + j) * (Gn * HWn)) = acc[j];
}

extern "C" void kernel_launch(void* const* d_in, const int* in_sizes, int n_in,
                              void* d_out, int out_size) {
    const float* x = (const float*)d_in[0];   // (8,256,56,56)
    const float* w = (const float*)d_in[1];   // (8,32,9,56,56)
    float* out = (float*)d_out;               // (8,256,56,56)

    SKA_20950850470021_kernel<<<NBLK, BTH>>>(x, w, out);
}

// round 15
// speedup vs baseline: 1.2965x; 1.2965x over previous
#include <cuda_runtime.h>
#include <cuda_bf16.h>
#include <cstdint>

#define Bn   8
#define Cn   256
#define Gn   32
#define CPG  8
#define Hn   56
#define Wn   56
#define HWn  3136          // 56*56
#define QW   14
#define ROWS 8             // output rows per block
#define BTH  224           // 14 q * 8 r * 2 jp(=4ch)
#define NBLK (Bn*Gn*(Hn/ROWS))   // 1792
#define CSTR 568           // x smem channel stride in floats (10*56 + 8 pad)
#define WROW 448           // w smem tap stride in floats (8*56)

__device__ __forceinline__ unsigned smem_u32(const void* p) {
    return (unsigned)__cvta_generic_to_shared(p);
}
__device__ __forceinline__ void bulk_g2s(unsigned dst, const float* src, unsigned bytes, unsigned mbar) {
    asm volatile("cp.async.bulk.shared::cta.global.mbarrier::complete_tx::bytes [%0], [%1], %2, [%3];"
                 :: "r"(dst), "l"(src), "r"(bytes), "r"(mbar) : "memory");
}

__global__ __launch_bounds__(BTH, 2)
void SKA_20950850470021_kernel(const float* __restrict__ x,
                               const float* __restrict__ w,
                               float* __restrict__ out) {
    __shared__ float sw[9 * WROW];          // 16128 B: 9 taps x 8 rows x 56
    __shared__ float sx[CPG * CSTR];        // 18176 B: 8 ch x 10 rows x 56 (+pad)
    __shared__ __align__(8) unsigned long long mbar;

    const int tid = threadIdx.x;
    const int bid = blockIdx.x;
    const int ht = bid % (Hn / ROWS);
    const int g  = (bid / (Hn / ROWS)) % Gn;
    const int b  = bid / ((Hn / ROWS) * Gn);
    const int h0 = ht * ROWS;

    const int q  = tid % QW;
    const int rj = tid / QW;
    const int r  = rj % ROWS;
    const int jp = rj / ROWS;          // 0..1 : which 4 channels
    const int h  = h0 + r;
    const int w0 = q * 4;
    const int lane = tid & 31;

    const int cb = (b * Cn + g) * HWn;
    const unsigned mb = smem_u32(&mbar);

    // x copy bounds (rows h0-1 .. h0+8 clipped to image)
    const int hs = (h0 > 0) ? h0 - 1 : 0;
    const int he = (h0 + 9 < Hn) ? h0 + 9 : Hn;      // exclusive
    const unsigned xbytes = (unsigned)(he - hs) * Wn * 4u;
    const unsigned total_tx = 9u * WROW * 4u + (unsigned)CPG * xbytes;

    if (tid == 0) {
        asm volatile("mbarrier.init.shared.b64 [%0], 1;" :: "r"(mb) : "memory");
    }
    __syncthreads();

    if (tid == 0) {
        asm volatile("mbarrier.arrive.expect_tx.shared.b64 _, [%0], %1;"
                     :: "r"(mb), "r"(total_tx) : "memory");
        // 9 weight tap chunks: rows h0..h0+7 contiguous per tap
        const float* wg = w + ((b * Gn + g) * 9) * HWn + h0 * Wn;
#pragma unroll
        for (int k = 0; k < 9; ++k)
            bulk_g2s(smem_u32(sw + k * WROW), wg + k * HWn, WROW * 4u, mb);
        // 8 x channel chunks: rows hs..he-1 contiguous per channel
        const int sro = hs - (h0 - 1);     // 0 or 1: smem row of first copied row
#pragma unroll
        for (int jj = 0; jj < CPG; ++jj)
            bulk_g2s(smem_u32(sx + jj * CSTR + sro * Wn),
                     x + cb + jj * (Gn * HWn) + hs * Wn, xbytes, mb);
    }

    // zero-fill clipped halo rows (only top/bottom tiles)
    if (h0 == 0) {
        for (int e = tid; e < CPG * Wn; e += BTH)
            sx[(e / Wn) * CSTR + (e % Wn)] = 0.f;                    // smem row 0
    } else if (h0 + ROWS == Hn) {
        for (int e = tid; e < CPG * Wn; e += BTH)
            sx[(e / Wn) * CSTR + 9 * Wn + (e % Wn)] = 0.f;           // smem row 9
    }
    __syncthreads();   // orders zero-fill; all threads past init

    // wait for all bulk copies (acquire)
    {
        unsigned done;
        asm volatile(
            "{\n\t.reg .pred p;\n\t"
            "mbarrier.try_wait.parity.acquire.cta.shared::cta.b64 p, [%1], 0;\n\t"
            "selp.b32 %0, 1, 0, p;\n\t}"
            : "=r"(done) : "r"(mb) : "memory");
        if (!done) {
            asm volatile(
                "{\n\t.reg .pred P1;\n\t"
                "WL_%=:\n\t"
                "mbarrier.try_wait.parity.acquire.cta.shared::cta.b64 P1, [%0], 0, 0x989680;\n\t"
                "@P1 bra.uni WD_%=;\n\t"
                "bra.uni WL_%=;\n\t"
                "WD_%=:\n\t}"
                :: "r"(mb) : "memory");
        }
    }

    // ---------- compute: w + x from smem, halo via shuffles ----------
    const float hasLf = (q > 0) ? 1.f : 0.f;
    const float hasRf = (q < QW - 1) ? 1.f : 0.f;
    const bool needL = (lane == 0)  && (q > 0);
    const bool needR = (lane == 31) && (q < QW - 1);

    float4 wk[9];
#pragma unroll
    for (int k = 0; k < 9; ++k)
        wk[k] = *reinterpret_cast<const float4*>(sw + k * WROW + r * Wn + w0);

    float4 acc[4];
#pragma unroll
    for (int j = 0; j < 4; ++j) acc[j] = make_float4(0.f, 0.f, 0.f, 0.f);

#pragma unroll
    for (int j = 0; j < 4; ++j) {
        const float* sc = sx + (jp * 4 + j) * CSTR;
#pragma unroll
        for (int rr = 0; rr < 3; ++rr) {
            const float* srow = sc + (r + rr) * Wn;   // image row h-1+rr (zero-filled OOB)
            float4 c = *reinterpret_cast<const float4*>(srow + w0);
            float lv = __shfl_up_sync(0xFFFFFFFFu, c.w, 1);
            float rv = __shfl_down_sync(0xFFFFFFFFu, c.x, 1);
            if (needL) lv = srow[w0 - 1];
            if (needR) rv = srow[w0 + 4];
            lv *= hasLf;
            rv *= hasRf;

            const float4 wk0 = wk[rr * 3 + 0];
            const float4 wk1 = wk[rr * 3 + 1];
            const float4 wk2 = wk[rr * 3 + 2];
            acc[j].x += lv  * wk0.x + c.x * wk1.x + c.y * wk2.x;
            acc[j].y += c.x * wk0.y + c.y * wk1.y + c.z * wk2.y;
            acc[j].z += c.y * wk0.z + c.z * wk1.z + c.w * wk2.z;
            acc[j].w += c.z * wk0.w + c.w * wk1.w + rv  * wk2.w;
        }
    }

    const int obase = cb + h * Wn + w0;
#pragma unroll
    for (int j = 0; j < 4; ++j)
        *reinterpret_cast<float4*>(out + obase + (jp * 4 + j) * (Gn * HWn)) = acc[j];
}

extern "C" void kernel_launch(void* const* d_in, const int* in_sizes, int n_in,
                              void* d_out, int out_size) {
    const float* x = (const float*)d_in[0];   // (8,256,56,56)
    const float* w = (const float*)d_in[1];   // (8,32,9,56,56)
    float* out = (float*)d_out;               // (8,256,56,56)

    SKA_20950850470021_kernel<<<NBLK, BTH>>>(x, w, out);
}